// round 16
// baseline (speedup 1.0000x reference)
#include <cuda_runtime.h>
#include <cuda_fp16.h>
#include <cstdint>

#define N_NODES 50000
#define N_EDGES 800000
#define DIM 128
#define N_LAYERS 5
#define SCAN_BLOCKS ((N_NODES + 255) / 256)   // 196
#define N_F4 (N_NODES * DIM / 4)              // 1,600,000 (= 2 * N_EDGES)
#define N_WELEM (N_LAYERS * DIM * DIM)        // 81,920

// ---------------------------------------------------------------------------
// Scratch (allocation-free rule: __device__ globals)
// ---------------------------------------------------------------------------
__device__ __half g_h[N_NODES * DIM];      // feature buffer A (ping-pong)
__device__ __half g_act[N_NODES * DIM];    // feature buffer B (ping-pong)
__device__ __half g_whi[N_WELEM];          // W hi, [l][n][k] (k contig)
__device__ __half g_wlo[N_WELEM];          // W lo, [l][n][k]
__device__ int    g_count[N_NODES];
__device__ int    g_rank[N_EDGES];         // edge rank within its dst bucket
__device__ int    g_rowptr[N_NODES + 1];
__device__ float  g_dinv[N_NODES];
__device__ int2   g_adj[N_EDGES];          // (src, bitcast(dinv[src]))
__device__ int    g_is64;
__device__ int    g_blocksum[SCAN_BLOCKS];
__device__ int    g_scanflag[SCAN_BLOCKS];

// ---------------------------------------------------------------------------
// Edge dtype handling (int64 vs int32 storage)
// ---------------------------------------------------------------------------
__device__ __forceinline__ int load_edge(const void* e, long long idx, int is64) {
    if (is64) return (int)((const long long*)e)[idx];
    return ((const int*)e)[idx];
}

// fused: detect dtype + zero counters/flags + split W into fp16 hi/lo [l][n][k]
__global__ void init_kernel(const void* e, const float* __restrict__ weights) {
    int i = blockIdx.x * blockDim.x + threadIdx.x;
    if (i < N_NODES) g_count[i] = 0;
    if (i < SCAN_BLOCKS) g_scanflag[i] = 0;
    if (i < N_WELEM) {
        int l = i / (DIM * DIM);
        int rem = i % (DIM * DIM);
        int k = rem / DIM;       // source row (k)
        int n = rem % DIM;       // source col (n)
        float v = weights[i];
        __half hi = __float2half_rn(v);
        __half lo = __float2half_rn(v - __half2float(hi));
        int o = l * DIM * DIM + n * DIM + k;   // [l][n][k]
        g_whi[o] = hi;
        g_wlo[o] = lo;
    }
    if (blockIdx.x == 0 && threadIdx.x == 0) {
        const unsigned* w = (const unsigned*)e;
        int is64 = 1;
        for (int k = 0; k < 128; k++)
            if (w[2 * k + 1] != 0u) { is64 = 0; break; }
        g_is64 = is64;
    }
}

// 2 edges per thread, vectorized dst loads; atomicAdd return value = rank
__global__ void hist_kernel(const void* e) {
    int i = blockIdx.x * blockDim.x + threadIdx.x;   // pair index
    if (2 * i >= N_EDGES) return;
    int d0, d1;
    if (g_is64) {
        longlong2 p = ((const longlong2*)e)[(N_EDGES + 2 * i) >> 1];
        d0 = (int)p.x; d1 = (int)p.y;
    } else {
        int2 p = ((const int2*)e)[(N_EDGES + 2 * i) >> 1];
        d0 = p.x; d1 = p.y;
    }
    g_rank[2 * i]     = atomicAdd(&g_count[d0], 1);
    g_rank[2 * i + 1] = atomicAdd(&g_count[d1], 1);
}

// ---------------------------------------------------------------------------
// Single-kernel exclusive scan (publish-then-spin) + fused dinv
// ---------------------------------------------------------------------------
__device__ __forceinline__ int warp_incl_scan(int x) {
#pragma unroll
    for (int o = 1; o < 32; o <<= 1) {
        int y = __shfl_up_sync(0xFFFFFFFFu, x, o);
        if ((threadIdx.x & 31) >= o) x += y;
    }
    return x;
}

__global__ void scan_kernel() {
    __shared__ int wsum[8];
    __shared__ int sh_off;
    int t = threadIdx.x, b = blockIdx.x;
    int i = b * 256 + t;
    int v = (i < N_NODES) ? g_count[i] : 0;
    if (i < N_NODES) g_dinv[i] = rsqrtf((float)(v + 1));  // fused dinv
    int x = warp_incl_scan(v);
    if ((t & 31) == 31) wsum[t >> 5] = x;
    if (t == 0) sh_off = 0;
    __syncthreads();
    if (t == 0) {
        int run = 0;
#pragma unroll
        for (int w = 0; w < 8; w++) { int tmp = wsum[w]; wsum[w] = run; run += tmp; }
        g_blocksum[b] = run;
        __threadfence();
        atomicExch(&g_scanflag[b], 1);
    }
    __syncthreads();
    if (t < b) {
        while (atomicAdd(&g_scanflag[t], 0) == 0) { }
        atomicAdd(&sh_off, g_blocksum[t]);
    }
    __syncthreads();
    if (i < N_NODES) g_rowptr[i] = sh_off + x - v + wsum[t >> 5];
    if (i == 0) g_rowptr[N_NODES] = N_EDGES;
}

// build CSR adjacency (no atomics — rank precomputed) + fused x->fp16 convert
__global__ void build_csr_kernel(const void* e, const float* __restrict__ x,
                                 __half* __restrict__ act) {
    int i = blockIdx.x * blockDim.x + threadIdx.x;
    if (i < N_EDGES) {
        int is64 = g_is64;
        int s = load_edge(e, i, is64);
        int d = load_edge(e, (long long)N_EDGES + i, is64);
        int pos = g_rowptr[d] + g_rank[i];
        g_adj[pos] = make_int2(s, __float_as_int(g_dinv[s]));
    }
#pragma unroll
    for (int v4 = i; v4 < N_F4; v4 += N_EDGES) {
        float4 v = __ldcs((const float4*)&x[(size_t)v4 * 4]);   // streaming read-once
        __half2 a = __floats2half2_rn(v.x, v.y);
        __half2 b = __floats2half2_rn(v.z, v.w);
        uint2 p = make_uint2(*(unsigned*)&a, *(unsigned*)&b);
        *(uint2*)&act[(size_t)v4 * 4] = p;
    }
}

// ---------------------------------------------------------------------------
// Shared mma / cp.async helpers
// ---------------------------------------------------------------------------
#define WSTR 136   // halves per W/act smem row (128 + 8 pad)
#define ASTR 40    // halves per A smem row (32 + 8 pad) -- gemm0 only

__device__ __forceinline__ void mma_fp16(float c[4], const unsigned a[4], const unsigned b[2]) {
    asm volatile(
        "mma.sync.aligned.m16n8k16.row.col.f32.f16.f16.f32 "
        "{%0,%1,%2,%3}, {%4,%5,%6,%7}, {%8,%9}, {%0,%1,%2,%3};"
        : "+f"(c[0]), "+f"(c[1]), "+f"(c[2]), "+f"(c[3])
        : "r"(a[0]), "r"(a[1]), "r"(a[2]), "r"(a[3]), "r"(b[0]), "r"(b[1]));
}

__device__ __forceinline__ void cp_async16(uint32_t saddr, const void* gaddr, int src_bytes) {
    asm volatile("cp.async.cg.shared.global [%0], [%1], 16, %2;"
                 :: "r"(saddr), "l"(gaddr), "r"(src_bytes));
}
__device__ __forceinline__ void cp_commit() {
    asm volatile("cp.async.commit_group;");
}
template <int N>
__device__ __forceinline__ void cp_wait() {
    asm volatile("cp.async.wait_group %0;" :: "n"(N));
}

// ---------------------------------------------------------------------------
// Layer-0 GEMM: BM=128 x BN=64, cp.async double buffer. (unchanged)
// ---------------------------------------------------------------------------
#define BN 64
#define GEMM_SMEM ((2 * BN * WSTR + 2 * 128 * ASTR) * 2)   // 55,296 B
#define N_ROWTILES ((N_NODES + 127) / 128)                  // 391
#define GEMM_GRID (N_ROWTILES * 2)                          // 782

__global__ __launch_bounds__(256) void gemm_fp16_kernel(
    const __half* __restrict__ A,
    const __half* __restrict__ Whi, const __half* __restrict__ Wlo,
    __half* __restrict__ C, int M)
{
    extern __shared__ __half smem[];
    __half (*Bhi)[WSTR] = (__half(*)[WSTR])smem;                 // [n][k], n 0..63
    __half (*Blo)[WSTR] = (__half(*)[WSTR])(smem + BN * WSTR);
    __half (*As)[128][ASTR] = (__half(*)[128][ASTR])(smem + 2 * BN * WSTR);

    int tid = threadIdx.x;
    int warp = tid >> 5;
    int lane = tid & 31;
    int g = lane >> 2;
    int t = lane & 3;
    int wm = warp & 3;
    int wn = warp >> 2;

    int rowTile = blockIdx.x >> 1;
    int nBase   = (blockIdx.x & 1) * BN;
    int rowBase = rowTile * 128;

#pragma unroll
    for (int i = 0; i < 4; i++) {
        int idx = tid + i * 256;
        int n = idx >> 4;
        int kc = (idx & 15) * 8;
        *(uint4*)&Bhi[n][kc] = *(const uint4*)&Whi[(size_t)(nBase + n) * DIM + kc];
        *(uint4*)&Blo[n][kc] = *(const uint4*)&Wlo[(size_t)(nBase + n) * DIM + kc];
    }

    auto issue_chunk = [&](int kc, int stage) {
#pragma unroll
        for (int i = 0; i < 2; i++) {
            int idx = tid + i * 256;
            int r = idx >> 2;
            int part = idx & 3;
            int grow = rowBase + r;
            int ok = (grow < M);
            const void* src = &A[(size_t)(ok ? grow : 0) * DIM + kc * 32 + part * 8];
            uint32_t dst = (uint32_t)__cvta_generic_to_shared(&As[stage][r][part * 8]);
            cp_async16(dst, src, ok ? 16 : 0);
        }
        cp_commit();
    };

    issue_chunk(0, 0);

    float c[2][4][4];
#pragma unroll
    for (int mt = 0; mt < 2; mt++)
#pragma unroll
        for (int j = 0; j < 4; j++)
#pragma unroll
            for (int e = 0; e < 4; e++) c[mt][j][e] = 0.0f;

    for (int kc = 0; kc < 4; kc++) {
        if (kc < 3) { issue_chunk(kc + 1, (kc + 1) & 1); cp_wait<1>(); }
        else        { cp_wait<0>(); }
        __syncthreads();

        int stage = kc & 1;
        int k0 = kc * 32;
#pragma unroll
        for (int kk = 0; kk < 2; kk++) {
            int ks = kk * 16;
            int ksg = k0 + ks;
            unsigned a[2][4];
#pragma unroll
            for (int mt = 0; mt < 2; mt++) {
                int row = wm * 32 + mt * 16;
                a[mt][0] = *(const unsigned*)&As[stage][row + g    ][ks + 2 * t];
                a[mt][1] = *(const unsigned*)&As[stage][row + g + 8][ks + 2 * t];
                a[mt][2] = *(const unsigned*)&As[stage][row + g    ][ks + 2 * t + 8];
                a[mt][3] = *(const unsigned*)&As[stage][row + g + 8][ks + 2 * t + 8];
            }
#pragma unroll
            for (int j = 0; j < 4; j++) {
                int n = wn * 32 + j * 8 + g;
                unsigned bh[2], bl[2];
                bh[0] = *(const unsigned*)&Bhi[n][ksg + 2 * t];
                bh[1] = *(const unsigned*)&Bhi[n][ksg + 2 * t + 8];
                bl[0] = *(const unsigned*)&Blo[n][ksg + 2 * t];
                bl[1] = *(const unsigned*)&Blo[n][ksg + 2 * t + 8];
#pragma unroll
                for (int mt = 0; mt < 2; mt++) {
                    mma_fp16(c[mt][j], a[mt], bh);
                    mma_fp16(c[mt][j], a[mt], bl);
                }
            }
        }
        __syncthreads();
    }

#pragma unroll
    for (int mt = 0; mt < 2; mt++) {
        int r0 = rowBase + wm * 32 + mt * 16 + g;
        int r1 = r0 + 8;
#pragma unroll
        for (int j = 0; j < 4; j++) {
            int col = nBase + wn * 32 + j * 8 + 2 * t;
            if (r0 < M) {
                __half2 p = __floats2half2_rn(c[mt][j][0], c[mt][j][1]);
                *(unsigned*)&C[(size_t)r0 * DIM + col] = *(unsigned*)&p;
            }
            if (r1 < M) {
                __half2 p = __floats2half2_rn(c[mt][j][2], c[mt][j][3]);
                *(unsigned*)&C[(size_t)r1 * DIM + col] = *(unsigned*)&p;
            }
        }
    }
}

// ---------------------------------------------------------------------------
// FUSED gather(l) + gemm(l+1) per 128-node tile. 512 threads, 16 warps.
// hin and hout are DISTINCT buffers (ping-pong) — fixes the R14 in-place race.
// smem = W hi/lo (69.6KB) + act tile (34.8KB) = 104.4KB -> 2/SM.
// ---------------------------------------------------------------------------
#define FUSED_SMEM ((3 * 128 * WSTR) * 2)   // 104,448 B

__global__ __launch_bounds__(512, 2) void fused_gather_gemm_kernel(
    const __half* __restrict__ hin, const float* __restrict__ bias,
    const __half* __restrict__ Whi, const __half* __restrict__ Wlo,
    __half* __restrict__ hout)
{
    extern __shared__ __half smem[];
    __half (*Bhi)[WSTR]  = (__half(*)[WSTR])smem;                  // [n][k], n 0..127
    __half (*Blo)[WSTR]  = (__half(*)[WSTR])(smem + 128 * WSTR);
    __half (*ActS)[WSTR] = (__half(*)[WSTR])(smem + 2 * 128 * WSTR); // [r][k]

    int tid = threadIdx.x;
    int warp = tid >> 5;     // 0..15
    int lane = tid & 31;
    int rowBase = blockIdx.x * 128;

    // ---- W copy (hi+lo, 128x128): 2048 uint4 each, 4 iters of 512 ----
#pragma unroll
    for (int i = 0; i < 4; i++) {
        int idx = tid + i * 512;          // 0..2047
        int n = idx >> 4;                 // 0..127
        int kc = (idx & 15) * 8;
        *(uint4*)&Bhi[n][kc] = *(const uint4*)&Whi[(size_t)n * DIM + kc];
        *(uint4*)&Blo[n][kc] = *(const uint4*)&Wlo[(size_t)n * DIM + kc];
    }

    // ---- Phase 1: gather 8 nodes per warp into ActS ----
    {
        int g16 = lane >> 4;
        int l16 = lane & 15;
        int c = l16 * 8;

        for (int r = warp; r < 128; r += 16) {
            int node = rowBase + r;
            float acc[8];
            float dd = 0.0f;
            if (node < N_NODES) {
                int start = g_rowptr[node];
                int end   = g_rowptr[node + 1];
                dd = g_dinv[node];

                uint4 p = __ldcg((const uint4*)&hin[(size_t)node * DIM + c]);
                const __half2* hp = (const __half2*)&p;
                float w0 = g16 ? 0.0f : dd;   // self loop counted once
#pragma unroll
                for (int i = 0; i < 4; i++) {
                    float2 f = __half22float2(hp[i]);
                    acc[2 * i]     = w0 * f.x;
                    acc[2 * i + 1] = w0 * f.y;
                }

                int j = start + g16;
                int2 ew = (j < end) ? g_adj[j] : make_int2(0, 0);
#pragma unroll 4
                while (j < end) {
                    int jn = j + 2;
                    int2 ewn = (jn < end) ? g_adj[jn] : make_int2(0, 0);
                    float w = __int_as_float(ew.y);
                    uint4 q = __ldcg((const uint4*)&hin[(size_t)ew.x * DIM + c]);
                    const __half2* qp = (const __half2*)&q;
#pragma unroll
                    for (int i = 0; i < 4; i++) {
                        float2 f = __half22float2(qp[i]);
                        acc[2 * i]     += w * f.x;
                        acc[2 * i + 1] += w * f.y;
                    }
                    ew = ewn;
                    j = jn;
                }
            } else {
#pragma unroll
                for (int i = 0; i < 8; i++) acc[i] = 0.0f;
            }

#pragma unroll
            for (int i = 0; i < 8; i++)
                acc[i] += __shfl_xor_sync(0xFFFFFFFFu, acc[i], 16);

            if (g16 == 0) {
                __half2 p0, p1, p2, p3;
                if (node < N_NODES) {
                    float4 b0 = *(const float4*)&bias[c];
                    float4 b1 = *(const float4*)&bias[c + 4];
                    p0 = __floats2half2_rn(fmaxf(dd * acc[0] + b0.x, 0.0f),
                                           fmaxf(dd * acc[1] + b0.y, 0.0f));
                    p1 = __floats2half2_rn(fmaxf(dd * acc[2] + b0.z, 0.0f),
                                           fmaxf(dd * acc[3] + b0.w, 0.0f));
                    p2 = __floats2half2_rn(fmaxf(dd * acc[4] + b1.x, 0.0f),
                                           fmaxf(dd * acc[5] + b1.y, 0.0f));
                    p3 = __floats2half2_rn(fmaxf(dd * acc[6] + b1.z, 0.0f),
                                           fmaxf(dd * acc[7] + b1.w, 0.0f));
                } else {
                    p0 = p1 = p2 = p3 = __floats2half2_rn(0.0f, 0.0f);
                }
                uint4 pk = make_uint4(*(unsigned*)&p0, *(unsigned*)&p1,
                                      *(unsigned*)&p2, *(unsigned*)&p3);
                *(uint4*)&ActS[r][c] = pk;
            }
        }
    }
    __syncthreads();   // act tile + W complete

    // ---- Phase 2: GEMM, 16 warps = 4(M) x 4(N), warp tile 32x32 ----
    {
        int g = lane >> 2;
        int t = lane & 3;
        int wm = warp & 3;       // 32 rows each
        int wn = warp >> 2;      // 32 cols each

        float c[2][4][4];
#pragma unroll
        for (int mt = 0; mt < 2; mt++)
#pragma unroll
            for (int j = 0; j < 4; j++)
#pragma unroll
                for (int e = 0; e < 4; e++) c[mt][j][e] = 0.0f;

#pragma unroll
        for (int kk = 0; kk < 8; kk++) {
            int ks = kk * 16;
            unsigned a[2][4];
#pragma unroll
            for (int mt = 0; mt < 2; mt++) {
                int row = wm * 32 + mt * 16;
                a[mt][0] = *(const unsigned*)&ActS[row + g    ][ks + 2 * t];
                a[mt][1] = *(const unsigned*)&ActS[row + g + 8][ks + 2 * t];
                a[mt][2] = *(const unsigned*)&ActS[row + g    ][ks + 2 * t + 8];
                a[mt][3] = *(const unsigned*)&ActS[row + g + 8][ks + 2 * t + 8];
            }
#pragma unroll
            for (int j = 0; j < 4; j++) {
                int n = wn * 32 + j * 8 + g;
                unsigned bh[2], bl[2];
                bh[0] = *(const unsigned*)&Bhi[n][ks + 2 * t];
                bh[1] = *(const unsigned*)&Bhi[n][ks + 2 * t + 8];
                bl[0] = *(const unsigned*)&Blo[n][ks + 2 * t];
                bl[1] = *(const unsigned*)&Blo[n][ks + 2 * t + 8];
#pragma unroll
                for (int mt = 0; mt < 2; mt++) {
                    mma_fp16(c[mt][j], a[mt], bh);
                    mma_fp16(c[mt][j], a[mt], bl);
                }
            }
        }

#pragma unroll
        for (int mt = 0; mt < 2; mt++) {
            int r0 = rowBase + wm * 32 + mt * 16 + g;
            int r1 = r0 + 8;
#pragma unroll
            for (int j = 0; j < 4; j++) {
                int col = wn * 32 + j * 8 + 2 * t;
                if (r0 < N_NODES) {
                    __half2 p = __floats2half2_rn(c[mt][j][0], c[mt][j][1]);
                    *(unsigned*)&hout[(size_t)r0 * DIM + col] = *(unsigned*)&p;
                }
                if (r1 < N_NODES) {
                    __half2 p = __floats2half2_rn(c[mt][j][2], c[mt][j][3]);
                    *(unsigned*)&hout[(size_t)r1 * DIM + col] = *(unsigned*)&p;
                }
            }
        }
    }
}

// ---------------------------------------------------------------------------
// Final gather (layer 4): fp32 output to d_out. Warp per node.
// ---------------------------------------------------------------------------
__global__ __launch_bounds__(256) void gather_final_kernel(
    const __half* __restrict__ h, const float* __restrict__ bias,
    float* __restrict__ out)
{
    int warp = (blockIdx.x * blockDim.x + threadIdx.x) >> 5;
    if (warp >= N_NODES) return;
    int lane = threadIdx.x & 31;
    int g16 = lane >> 4;
    int l16 = lane & 15;
    int node = warp;
    int c = l16 * 8;

    int start = g_rowptr[node];
    int end   = g_rowptr[node + 1];
    float dd  = g_dinv[node];

    float acc[8];
    {
        uint4 p = __ldcg((const uint4*)&h[(size_t)node * DIM + c]);
        const __half2* hp = (const __half2*)&p;
        float w0 = g16 ? 0.0f : dd;
#pragma unroll
        for (int i = 0; i < 4; i++) {
            float2 f = __half22float2(hp[i]);
            acc[2 * i]     = w0 * f.x;
            acc[2 * i + 1] = w0 * f.y;
        }
    }

    int j = start + g16;
    int2 ew = (j < end) ? g_adj[j] : make_int2(0, 0);
#pragma unroll 4
    while (j < end) {
        int jn = j + 2;
        int2 ewn = (jn < end) ? g_adj[jn] : make_int2(0, 0);
        float w = __int_as_float(ew.y);
        uint4 p = __ldcg((const uint4*)&h[(size_t)ew.x * DIM + c]);
        const __half2* hp = (const __half2*)&p;
#pragma unroll
        for (int i = 0; i < 4; i++) {
            float2 f = __half22float2(hp[i]);
            acc[2 * i]     += w * f.x;
            acc[2 * i + 1] += w * f.y;
        }
        ew = ewn;
        j = jn;
    }

#pragma unroll
    for (int i = 0; i < 8; i++)
        acc[i] += __shfl_xor_sync(0xFFFFFFFFu, acc[i], 16);

    if (g16 == 0) {
        float4 b0 = *(const float4*)&bias[c];
        float4 b1 = *(const float4*)&bias[c + 4];
        float* o = out + (size_t)node * DIM + c;
        *(float4*)&o[0] = make_float4(fmaxf(dd * acc[0] + b0.x, 0.0f),
                                      fmaxf(dd * acc[1] + b0.y, 0.0f),
                                      fmaxf(dd * acc[2] + b0.z, 0.0f),
                                      fmaxf(dd * acc[3] + b0.w, 0.0f));
        *(float4*)&o[4] = make_float4(fmaxf(dd * acc[4] + b1.x, 0.0f),
                                      fmaxf(dd * acc[5] + b1.y, 0.0f),
                                      fmaxf(dd * acc[6] + b1.z, 0.0f),
                                      fmaxf(dd * acc[7] + b1.w, 0.0f));
    }
}

// ---------------------------------------------------------------------------
// Launch
// ---------------------------------------------------------------------------
extern "C" void kernel_launch(void* const* d_in, const int* in_sizes, int n_in,
                              void* d_out, int out_size)
{
    const float* x       = (const float*)d_in[0];
    const void*  eidx    = d_in[1];
    const float* weights = (const float*)d_in[2];
    const float* biases  = (const float*)d_in[3];
    float*       out     = (float*)d_out;

    __half* bufA; cudaGetSymbolAddress((void**)&bufA, g_h);
    __half* bufB; cudaGetSymbolAddress((void**)&bufB, g_act);
    __half* whi;  cudaGetSymbolAddress((void**)&whi,  g_whi);
    __half* wlo;  cudaGetSymbolAddress((void**)&wlo,  g_wlo);

    static int smem_set = 0;
    if (!smem_set) {
        cudaFuncSetAttribute(gemm_fp16_kernel,
                             cudaFuncAttributeMaxDynamicSharedMemorySize, GEMM_SMEM);
        cudaFuncSetAttribute(fused_gather_gemm_kernel,
                             cudaFuncAttributeMaxDynamicSharedMemorySize, FUSED_SMEM);
        smem_set = 1;
    }

    // ---- Prologue (4 kernels). x-fp16 goes into bufB. ----
    init_kernel<<<(N_WELEM + 255) / 256, 256>>>(eidx, weights);
    hist_kernel<<<(N_EDGES / 2 + 255) / 256, 256>>>(eidx);
    scan_kernel<<<SCAN_BLOCKS, 256>>>();
    build_csr_kernel<<<(N_EDGES + 255) / 256, 256>>>(eidx, x, bufB);

    // ---- Layer 0 GEMM: bufA = bufB @ W0 ----
    gemm_fp16_kernel<<<GEMM_GRID, 256, GEMM_SMEM>>>(bufB, whi, wlo, bufA, N_NODES);

    // ---- Layers 1..4: fused gather(prev h) + gemm(l), PING-PONG buffers ----
    __half* cur = bufA;   // holds h of layer l-1
    __half* nxt = bufB;
    for (int l = 1; l < N_LAYERS; l++) {
        const float* b = biases + (size_t)(l - 1) * DIM;
        fused_gather_gemm_kernel<<<N_ROWTILES, 512, FUSED_SMEM>>>(
            cur, b, whi + (size_t)l * DIM * DIM, wlo + (size_t)l * DIM * DIM, nxt);
        __half* tmp = cur; cur = nxt; nxt = tmp;
    }

    // ---- Final gather (layer 4) -> fp32 out; cur holds h4 ----
    gather_final_kernel<<<(N_NODES * 32 + 255) / 256, 256>>>(
        cur, biases + (size_t)(N_LAYERS - 1) * DIM, out);
}

// round 17
// speedup vs baseline: 1.1287x; 1.1287x over previous
#include <cuda_runtime.h>
#include <cuda_fp16.h>
#include <cstdint>

#define N_NODES 50000
#define N_EDGES 800000
#define DIM 128
#define N_LAYERS 5
#define SCAN_BLOCKS ((N_NODES + 255) / 256)   // 196
#define N_F4 (N_NODES * DIM / 4)              // 1,600,000
#define N_WELEM (N_LAYERS * DIM * DIM)        // 81,920

// ---------------------------------------------------------------------------
// Scratch (allocation-free rule: __device__ globals)
// ---------------------------------------------------------------------------
__device__ __half g_h[N_NODES * DIM];      // post-GEMM features (fp16)
__device__ __half g_act[N_NODES * DIM];    // layer activations (fp16)
__device__ __half g_whi[N_WELEM];          // W hi, [l][n][k] (k contig)
__device__ __half g_wlo[N_WELEM];          // W lo, [l][n][k]
__device__ int    g_count[N_NODES];
__device__ int    g_rank[N_EDGES];         // edge rank within its dst bucket
__device__ int    g_rowptr[N_NODES + 1];
__device__ float  g_dinv[N_NODES];
__device__ int2   g_adj[N_EDGES];          // (src, bitcast(dinv[src]))
__device__ int    g_is64;
__device__ int    g_blocksum[SCAN_BLOCKS];
__device__ int    g_scanflag[SCAN_BLOCKS];

// ---------------------------------------------------------------------------
// Edge dtype handling (int64 vs int32 storage)
// ---------------------------------------------------------------------------
__device__ __forceinline__ int load_edge(const void* e, long long idx, int is64) {
    if (is64) return (int)((const long long*)e)[idx];
    return ((const int*)e)[idx];
}

// fused: detect dtype + zero counters/flags + split W into fp16 hi/lo [l][n][k]
__global__ void init_kernel(const void* e, const float* __restrict__ weights) {
    int i = blockIdx.x * blockDim.x + threadIdx.x;
    if (i < N_NODES) g_count[i] = 0;
    if (i < SCAN_BLOCKS) g_scanflag[i] = 0;
    if (i < N_WELEM) {
        int l = i / (DIM * DIM);
        int rem = i % (DIM * DIM);
        int k = rem / DIM;       // source row (k)
        int n = rem % DIM;       // source col (n)
        float v = weights[i];
        __half hi = __float2half_rn(v);
        __half lo = __float2half_rn(v - __half2float(hi));
        int o = l * DIM * DIM + n * DIM + k;   // [l][n][k]
        g_whi[o] = hi;
        g_wlo[o] = lo;
    }
    if (blockIdx.x == 0 && threadIdx.x == 0) {
        const unsigned* w = (const unsigned*)e;
        int is64 = 1;
        for (int k = 0; k < 128; k++)
            if (w[2 * k + 1] != 0u) { is64 = 0; break; }
        g_is64 = is64;
    }
}

// 2 edges per thread, vectorized dst loads; atomicAdd return value = rank
__global__ void hist_kernel(const void* e) {
    int i = blockIdx.x * blockDim.x + threadIdx.x;   // pair index
    if (2 * i >= N_EDGES) return;
    int d0, d1;
    if (g_is64) {
        longlong2 p = ((const longlong2*)e)[(N_EDGES + 2 * i) >> 1];
        d0 = (int)p.x; d1 = (int)p.y;
    } else {
        int2 p = ((const int2*)e)[(N_EDGES + 2 * i) >> 1];
        d0 = p.x; d1 = p.y;
    }
    g_rank[2 * i]     = atomicAdd(&g_count[d0], 1);
    g_rank[2 * i + 1] = atomicAdd(&g_count[d1], 1);
}

// ---------------------------------------------------------------------------
// Single-kernel exclusive scan (publish-then-spin) + fused dinv
// ---------------------------------------------------------------------------
__device__ __forceinline__ int warp_incl_scan(int x) {
#pragma unroll
    for (int o = 1; o < 32; o <<= 1) {
        int y = __shfl_up_sync(0xFFFFFFFFu, x, o);
        if ((threadIdx.x & 31) >= o) x += y;
    }
    return x;
}

__global__ void scan_kernel() {
    __shared__ int wsum[8];
    __shared__ int sh_off;
    int t = threadIdx.x, b = blockIdx.x;
    int i = b * 256 + t;
    int v = (i < N_NODES) ? g_count[i] : 0;
    if (i < N_NODES) g_dinv[i] = rsqrtf((float)(v + 1));  // fused dinv
    int x = warp_incl_scan(v);
    if ((t & 31) == 31) wsum[t >> 5] = x;
    if (t == 0) sh_off = 0;
    __syncthreads();
    if (t == 0) {
        int run = 0;
#pragma unroll
        for (int w = 0; w < 8; w++) { int tmp = wsum[w]; wsum[w] = run; run += tmp; }
        g_blocksum[b] = run;
        __threadfence();
        atomicExch(&g_scanflag[b], 1);
    }
    __syncthreads();
    if (t < b) {
        while (atomicAdd(&g_scanflag[t], 0) == 0) { }
        atomicAdd(&sh_off, g_blocksum[t]);
    }
    __syncthreads();
    if (i < N_NODES) g_rowptr[i] = sh_off + x - v + wsum[t >> 5];
    if (i == 0) g_rowptr[N_NODES] = N_EDGES;
}

// build CSR adjacency only (no atomics — rank precomputed)
__global__ void build_adj_kernel(const void* e) {
    int i = blockIdx.x * blockDim.x + threadIdx.x;
    if (i < N_EDGES) {
        int is64 = g_is64;
        int s = load_edge(e, i, is64);
        int d = load_edge(e, (long long)N_EDGES + i, is64);
        int pos = g_rowptr[d] + g_rank[i];
        g_adj[pos] = make_int2(s, __float_as_int(g_dinv[s]));
    }
}

// x (fp32) -> act (fp16), 2 float4 per thread, streaming reads
__global__ void convert_x_kernel(const float* __restrict__ x, __half* __restrict__ act) {
    int i = blockIdx.x * blockDim.x + threadIdx.x;
#pragma unroll
    for (int v4 = i; v4 < N_F4; v4 += N_F4 / 2) {
        float4 v = __ldcs((const float4*)&x[(size_t)v4 * 4]);
        __half2 a = __floats2half2_rn(v.x, v.y);
        __half2 b = __floats2half2_rn(v.z, v.w);
        uint2 p = make_uint2(*(unsigned*)&a, *(unsigned*)&b);
        *(uint2*)&act[(size_t)v4 * 4] = p;
    }
}

// ---------------------------------------------------------------------------
// Shared mma / cp.async helpers
// ---------------------------------------------------------------------------
#define WSTR 136   // halves per W smem row (128 + 8 pad)
#define ASTR 40    // halves per A smem row (32 + 8 pad)

__device__ __forceinline__ void mma_fp16(float c[4], const unsigned a[4], const unsigned b[2]) {
    asm volatile(
        "mma.sync.aligned.m16n8k16.row.col.f32.f16.f16.f32 "
        "{%0,%1,%2,%3}, {%4,%5,%6,%7}, {%8,%9}, {%0,%1,%2,%3};"
        : "+f"(c[0]), "+f"(c[1]), "+f"(c[2]), "+f"(c[3])
        : "r"(a[0]), "r"(a[1]), "r"(a[2]), "r"(a[3]), "r"(b[0]), "r"(b[1]));
}

__device__ __forceinline__ void cp_async16(uint32_t saddr, const void* gaddr, int src_bytes) {
    asm volatile("cp.async.cg.shared.global [%0], [%1], 16, %2;"
                 :: "r"(saddr), "l"(gaddr), "r"(src_bytes));
}
__device__ __forceinline__ void cp_commit() {
    asm volatile("cp.async.commit_group;");
}
template <int N>
__device__ __forceinline__ void cp_wait() {
    asm volatile("cp.async.wait_group %0;" :: "n"(N));
}

// ---------------------------------------------------------------------------
// fp16 tensor-core GEMM: BM=128 x BN=64, cp.async double-buffered A staging.
// W pre-split (hi/lo fp16, [n][k]) -> vector copies into smem.
// smem = W(34.8KB) + 2xA(20.5KB) = 55.3KB -> 4 blocks/SM.
// ---------------------------------------------------------------------------
#define BN 64
#define GEMM_SMEM ((2 * BN * WSTR + 2 * 128 * ASTR) * 2)   // 55,296 B
#define N_ROWTILES ((N_NODES + 127) / 128)                  // 391
#define GEMM_GRID (N_ROWTILES * 2)                          // 782

__global__ __launch_bounds__(256) void gemm_fp16_kernel(
    const __half* __restrict__ A,
    const __half* __restrict__ Whi, const __half* __restrict__ Wlo,
    __half* __restrict__ C, int M)
{
    extern __shared__ __half smem[];
    __half (*Bhi)[WSTR] = (__half(*)[WSTR])smem;                 // [n][k], n 0..63
    __half (*Blo)[WSTR] = (__half(*)[WSTR])(smem + BN * WSTR);
    __half (*As)[128][ASTR] = (__half(*)[128][ASTR])(smem + 2 * BN * WSTR);

    int tid = threadIdx.x;
    int warp = tid >> 5;
    int lane = tid & 31;
    int g = lane >> 2;
    int t = lane & 3;
    int wm = warp & 3;
    int wn = warp >> 2;

    int rowTile = blockIdx.x >> 1;
    int nBase   = (blockIdx.x & 1) * BN;
    int rowBase = rowTile * 128;

#pragma unroll
    for (int i = 0; i < 4; i++) {
        int idx = tid + i * 256;
        int n = idx >> 4;
        int kc = (idx & 15) * 8;
        *(uint4*)&Bhi[n][kc] = *(const uint4*)&Whi[(size_t)(nBase + n) * DIM + kc];
        *(uint4*)&Blo[n][kc] = *(const uint4*)&Wlo[(size_t)(nBase + n) * DIM + kc];
    }

    auto issue_chunk = [&](int kc, int stage) {
#pragma unroll
        for (int i = 0; i < 2; i++) {
            int idx = tid + i * 256;
            int r = idx >> 2;
            int part = idx & 3;
            int grow = rowBase + r;
            int ok = (grow < M);
            const void* src = &A[(size_t)(ok ? grow : 0) * DIM + kc * 32 + part * 8];
            uint32_t dst = (uint32_t)__cvta_generic_to_shared(&As[stage][r][part * 8]);
            cp_async16(dst, src, ok ? 16 : 0);
        }
        cp_commit();
    };

    issue_chunk(0, 0);

    float c[2][4][4];
#pragma unroll
    for (int mt = 0; mt < 2; mt++)
#pragma unroll
        for (int j = 0; j < 4; j++)
#pragma unroll
            for (int e = 0; e < 4; e++) c[mt][j][e] = 0.0f;

    for (int kc = 0; kc < 4; kc++) {
        if (kc < 3) { issue_chunk(kc + 1, (kc + 1) & 1); cp_wait<1>(); }
        else        { cp_wait<0>(); }
        __syncthreads();

        int stage = kc & 1;
        int k0 = kc * 32;
#pragma unroll
        for (int kk = 0; kk < 2; kk++) {
            int ks = kk * 16;
            int ksg = k0 + ks;
            unsigned a[2][4];
#pragma unroll
            for (int mt = 0; mt < 2; mt++) {
                int row = wm * 32 + mt * 16;
                a[mt][0] = *(const unsigned*)&As[stage][row + g    ][ks + 2 * t];
                a[mt][1] = *(const unsigned*)&As[stage][row + g + 8][ks + 2 * t];
                a[mt][2] = *(const unsigned*)&As[stage][row + g    ][ks + 2 * t + 8];
                a[mt][3] = *(const unsigned*)&As[stage][row + g + 8][ks + 2 * t + 8];
            }
#pragma unroll
            for (int j = 0; j < 4; j++) {
                int n = wn * 32 + j * 8 + g;
                unsigned bh[2], bl[2];
                bh[0] = *(const unsigned*)&Bhi[n][ksg + 2 * t];
                bh[1] = *(const unsigned*)&Bhi[n][ksg + 2 * t + 8];
                bl[0] = *(const unsigned*)&Blo[n][ksg + 2 * t];
                bl[1] = *(const unsigned*)&Blo[n][ksg + 2 * t + 8];
#pragma unroll
                for (int mt = 0; mt < 2; mt++) {
                    mma_fp16(c[mt][j], a[mt], bh);
                    mma_fp16(c[mt][j], a[mt], bl);
                }
            }
        }
        __syncthreads();
    }

#pragma unroll
    for (int mt = 0; mt < 2; mt++) {
        int r0 = rowBase + wm * 32 + mt * 16 + g;
        int r1 = r0 + 8;
#pragma unroll
        for (int j = 0; j < 4; j++) {
            int col = nBase + wn * 32 + j * 8 + 2 * t;
            if (r0 < M) {
                __half2 p = __floats2half2_rn(c[mt][j][0], c[mt][j][1]);
                *(unsigned*)&C[(size_t)r0 * DIM + col] = *(unsigned*)&p;
            }
            if (r1 < M) {
                __half2 p = __floats2half2_rn(c[mt][j][2], c[mt][j][3]);
                *(unsigned*)&C[(size_t)r1 * DIM + col] = *(unsigned*)&p;
            }
        }
    }
}

// ---------------------------------------------------------------------------
// Fused CSR gather + self loop + scale + bias + ReLU.
// Warp per node, HALF-WARP per edge; adjacency software-prefetched.
// ---------------------------------------------------------------------------
__global__ __launch_bounds__(256) void gather_kernel(
    const __half* __restrict__ h, const float* __restrict__ bias,
    void* __restrict__ out, int out_half)
{
    int warp = (blockIdx.x * blockDim.x + threadIdx.x) >> 5;
    if (warp >= N_NODES) return;
    int lane = threadIdx.x & 31;
    int g16 = lane >> 4;     // half-warp id (0: even edges, 1: odd edges)
    int l16 = lane & 15;
    int node = warp;
    int c = l16 * 8;         // 8 consecutive halves per lane

    int start = g_rowptr[node];
    int end   = g_rowptr[node + 1];
    float dd  = g_dinv[node];

    float acc[8];
    {
        uint4 p = __ldcg((const uint4*)&h[(size_t)node * DIM + c]);
        const __half2* hp = (const __half2*)&p;
        float w0 = g16 ? 0.0f : dd;   // self loop counted once
#pragma unroll
        for (int i = 0; i < 4; i++) {
            float2 f = __half22float2(hp[i]);
            acc[2 * i]     = w0 * f.x;
            acc[2 * i + 1] = w0 * f.y;
        }
    }

    int j = start + g16;
    int2 ew = (j < end) ? g_adj[j] : make_int2(0, 0);
#pragma unroll 4
    while (j < end) {
        int jn = j + 2;
        int2 ewn = (jn < end) ? g_adj[jn] : make_int2(0, 0);
        float w = __int_as_float(ew.y);
        uint4 p = __ldcg((const uint4*)&h[(size_t)ew.x * DIM + c]);
        const __half2* hp = (const __half2*)&p;
#pragma unroll
        for (int i = 0; i < 4; i++) {
            float2 f = __half22float2(hp[i]);
            acc[2 * i]     += w * f.x;
            acc[2 * i + 1] += w * f.y;
        }
        ew = ewn;
        j = jn;
    }

#pragma unroll
    for (int i = 0; i < 8; i++)
        acc[i] += __shfl_xor_sync(0xFFFFFFFFu, acc[i], 16);

    if (g16 == 0) {
        float4 b0 = *(const float4*)&bias[c];
        float4 b1 = *(const float4*)&bias[c + 4];
        float r[8];
        r[0] = fmaxf(dd * acc[0] + b0.x, 0.0f);
        r[1] = fmaxf(dd * acc[1] + b0.y, 0.0f);
        r[2] = fmaxf(dd * acc[2] + b0.z, 0.0f);
        r[3] = fmaxf(dd * acc[3] + b0.w, 0.0f);
        r[4] = fmaxf(dd * acc[4] + b1.x, 0.0f);
        r[5] = fmaxf(dd * acc[5] + b1.y, 0.0f);
        r[6] = fmaxf(dd * acc[6] + b1.z, 0.0f);
        r[7] = fmaxf(dd * acc[7] + b1.w, 0.0f);

        if (out_half) {
            __half2 p0 = __floats2half2_rn(r[0], r[1]);
            __half2 p1 = __floats2half2_rn(r[2], r[3]);
            __half2 p2 = __floats2half2_rn(r[4], r[5]);
            __half2 p3 = __floats2half2_rn(r[6], r[7]);
            uint4 pk = make_uint4(*(unsigned*)&p0, *(unsigned*)&p1,
                                  *(unsigned*)&p2, *(unsigned*)&p3);
            *(uint4*)&((__half*)out)[(size_t)node * DIM + c] = pk;
        } else {
            float* o = (float*)out + (size_t)node * DIM + c;
            *(float4*)&o[0] = make_float4(r[0], r[1], r[2], r[3]);
            *(float4*)&o[4] = make_float4(r[4], r[5], r[6], r[7]);
        }
    }
}

// ---------------------------------------------------------------------------
// Launch: forked prologue (CSR chain on default stream; convert+gemm0 on s2)
// ---------------------------------------------------------------------------
extern "C" void kernel_launch(void* const* d_in, const int* in_sizes, int n_in,
                              void* d_out, int out_size)
{
    const float* x       = (const float*)d_in[0];
    const void*  eidx    = d_in[1];
    const float* weights = (const float*)d_in[2];
    const float* biases  = (const float*)d_in[3];
    float*       out     = (float*)d_out;

    __half* h;   cudaGetSymbolAddress((void**)&h,   g_h);
    __half* act; cudaGetSymbolAddress((void**)&act, g_act);
    __half* whi; cudaGetSymbolAddress((void**)&whi, g_whi);
    __half* wlo; cudaGetSymbolAddress((void**)&wlo, g_wlo);

    static cudaStream_t s2 = nullptr;
    static cudaEvent_t evFork = nullptr, evJoin = nullptr;
    static int setup_done = 0;
    if (!setup_done) {
        cudaFuncSetAttribute(gemm_fp16_kernel,
                             cudaFuncAttributeMaxDynamicSharedMemorySize, GEMM_SMEM);
        cudaStreamCreateWithFlags(&s2, cudaStreamNonBlocking);
        cudaEventCreateWithFlags(&evFork, cudaEventDisableTiming);
        cudaEventCreateWithFlags(&evJoin, cudaEventDisableTiming);
        setup_done = 1;
    }

    // ---- init (W split + counters + dtype) on main stream ----
    init_kernel<<<(N_WELEM + 255) / 256, 256>>>(eidx, weights);

    // ---- fork: s2 runs convert_x -> gemm0 (independent of CSR chain) ----
    cudaEventRecord(evFork, 0);
    cudaStreamWaitEvent(s2, evFork, 0);
    convert_x_kernel<<<(N_F4 / 2 + 255) / 256, 256, 0, s2>>>(x, act);
    gemm_fp16_kernel<<<GEMM_GRID, 256, GEMM_SMEM, s2>>>(act, whi, wlo, h, N_NODES);
    cudaEventRecord(evJoin, s2);

    // ---- main stream: CSR chain ----
    hist_kernel<<<(N_EDGES / 2 + 255) / 256, 256>>>(eidx);
    scan_kernel<<<SCAN_BLOCKS, 256>>>();
    build_adj_kernel<<<(N_EDGES + 255) / 256, 256>>>(eidx);

    // ---- join: gather0 needs both CSR (main) and gemm0 (s2) ----
    cudaStreamWaitEvent(0, evJoin, 0);

    const int gather_blocks = (N_NODES * 32 + 255) / 256;

    for (int l = 0; l < N_LAYERS; l++) {
        const float* b = biases + (size_t)l * DIM;
        int last = (l == N_LAYERS - 1);

        gather_kernel<<<gather_blocks, 256>>>(h, b, last ? (void*)out : (void*)act, !last);
        if (!last) {
            gemm_fp16_kernel<<<GEMM_GRID, 256, GEMM_SMEM>>>(
                act, whi + (size_t)(l + 1) * DIM * DIM,
                wlo + (size_t)(l + 1) * DIM * DIM, h, N_NODES);
        }
    }
}